// round 11
// baseline (speedup 1.0000x reference)
#include <cuda_runtime.h>
#include <cuda_bf16.h>
#include <cstdint>

// Problem constants
#define B_ROWS   8192
#define D_IN     768
#define D_HID    12288
#define TOPK_K   64
#define NCAND    128
#define WANT     96

// Output layout (floats): x_hat, residual, h, f, indices, pre_acts
#define XHAT_OFF 0LL
#define RES_OFF  6291456LL
#define H_OFF    12582912LL
#define F_OFF    113246208LL
#define IDX_OFF  213909504LL
#define PRE_OFF  214433792LL

// -------------------- device scratch --------------------
__device__ float g_WdT[(size_t)D_HID * D_IN];
__device__ float g_tv[(size_t)B_ROWS * TOPK_K];
__device__ int   g_tix[(size_t)B_ROWS * TOPK_K];
__device__ int   g_cand[(size_t)B_ROWS * NCAND];
__device__ int   g_ccnt[B_ROWS];

// -------------------- packed f32x2 helpers --------------------
__device__ __forceinline__ void ffma2(unsigned long long& d, unsigned long long a, unsigned long long b) {
    asm("fma.rn.f32x2 %0, %1, %2, %0;" : "+l"(d) : "l"(a), "l"(b));
}
__device__ __forceinline__ unsigned long long pk2(float lo, float hi) {
    unsigned long long r;
    asm("mov.b64 %0, {%1, %2};" : "=l"(r) : "f"(lo), "f"(hi));
    return r;
}
__device__ __forceinline__ float2 upk2(unsigned long long v) {
    float2 r;
    asm("mov.b64 {%0, %1}, %2;" : "=f"(r.x), "=f"(r.y) : "l"(v));
    return r;
}

// -------------------- K0b: transpose W_dec -> g_WdT --------------------
__global__ void transpose_kernel(const float* __restrict__ Wd) {
    __shared__ float tile[32][33];
    int x = blockIdx.x * 32 + threadIdx.x;
    int y = blockIdx.y * 32 + threadIdx.y;
    #pragma unroll
    for (int i = 0; i < 32; i += 8)
        tile[threadIdx.y + i][threadIdx.x] = Wd[(size_t)(y + i) * D_HID + x];
    __syncthreads();
    int xo = blockIdx.y * 32 + threadIdx.x;
    int yo = blockIdx.x * 32 + threadIdx.y;
    #pragma unroll
    for (int i = 0; i < 32; i += 8)
        g_WdT[(size_t)(yo + i) * D_IN + xo] = tile[threadIdx.x][threadIdx.y + i];
}

// -------------------- K1: approx encode GEMM (candidate gen + pre_acts @1e-3) ------------
#define BM 128
#define BN 64
#define BK 8

__global__ __launch_bounds__(256, 2)
void gemm_enc_kernel(const float* __restrict__ X,
                     const float* __restrict__ W,
                     const float* __restrict__ pre_bias,
                     const float* __restrict__ latent_bias,
                     float* __restrict__ out) {
    __shared__ float As[BK][BM];
    __shared__ float Bs[BK][BN];

    const int tid = threadIdx.x;
    const int bm = blockIdx.y * BM;
    const int bn = blockIdx.x * BN;
    const int tx = tid & 15;
    const int ty = tid >> 4;

    unsigned long long acc[8][2];
    #pragma unroll
    for (int i = 0; i < 8; i++) { acc[i][0] = 0ULL; acc[i][1] = 0ULL; }

    const int ar = tid >> 1;
    const int ac = (tid & 1) * 4;

    #pragma unroll 1
    for (int k0 = 0; k0 < D_IN; k0 += BK) {
        {
            float4 pb = *(const float4*)&pre_bias[k0 + ac];
            float4 va = *(const float4*)&X[(size_t)(bm + ar) * D_IN + k0 + ac];
            As[ac + 0][ar] = va.x - pb.x; As[ac + 1][ar] = va.y - pb.y;
            As[ac + 2][ar] = va.z - pb.z; As[ac + 3][ar] = va.w - pb.w;
        }
        if (tid < 128) {
            float4 vb = *(const float4*)&W[(size_t)(bn + ar) * D_IN + k0 + ac];
            Bs[ac + 0][ar] = vb.x; Bs[ac + 1][ar] = vb.y;
            Bs[ac + 2][ar] = vb.z; Bs[ac + 3][ar] = vb.w;
        }
        __syncthreads();

        #pragma unroll
        for (int kk = 0; kk < BK; kk++) {
            float4 b = *(const float4*)&Bs[kk][tx * 4];
            unsigned long long w0 = pk2(b.x, b.y);
            unsigned long long w1 = pk2(b.z, b.w);
            float4 a0 = *(const float4*)&As[kk][ty * 8];
            float4 a1 = *(const float4*)&As[kk][ty * 8 + 4];
            float av[8] = {a0.x, a0.y, a0.z, a0.w, a1.x, a1.y, a1.z, a1.w};
            #pragma unroll
            for (int i = 0; i < 8; i++) {
                unsigned long long ad = pk2(av[i], av[i]);
                ffma2(acc[i][0], ad, w0);
                ffma2(acc[i][1], ad, w1);
            }
        }
        __syncthreads();
    }

    float4 lb = *(const float4*)&latent_bias[bn + tx * 4];
    #pragma unroll
    for (int i = 0; i < 8; i++) {
        float2 p0 = upk2(acc[i][0]);
        float2 p1 = upk2(acc[i][1]);
        float4 v = make_float4(p0.x + lb.x, p0.y + lb.y, p1.x + lb.z, p1.y + lb.w);
        *(float4*)&out[(size_t)(bm + ty * 8 + i) * D_HID + bn + tx * 4] = v;
    }
}

// -------------------- K2: zero h and f regions --------------------
__global__ void zero_kernel(float4* __restrict__ p, long long n4) {
    long long i = (long long)blockIdx.x * blockDim.x + threadIdx.x;
    long long stride = (long long)gridDim.x * blockDim.x;
    float4 z = make_float4(0.f, 0.f, 0.f, 0.f);
    for (; i < n4; i += stride) p[i] = z;
}

// -------------------- key transforms --------------------
__device__ __forceinline__ unsigned to_key(float f) {
    unsigned u = __float_as_uint(f);
    return u ^ (((unsigned)((int)u >> 31)) | 0x80000000u);
}
__device__ __forceinline__ float from_key(unsigned k) {
    unsigned u = (k & 0x80000000u) ? (k ^ 0x80000000u) : ~k;
    return __uint_as_float(u);
}

// -------------------- K3: per-row top-96 candidate radix select --------------------
__global__ __launch_bounds__(256)
void topk_select_kernel(const float* __restrict__ pre) {
    extern __shared__ unsigned keys[];
    __shared__ unsigned hist[256];
    __shared__ unsigned s_prefix;
    __shared__ int s_remaining, s_cnt, s_ecnt;

    const int tid = threadIdx.x;
    const int row = blockIdx.x;
    const float* prow = pre + (size_t)row * D_HID;
    int* cand = g_cand + (size_t)row * NCAND;

    if (tid == 0) { s_prefix = 0u; s_remaining = WANT; s_cnt = 0; s_ecnt = 0; }
    for (int i = tid; i < D_HID; i += 256) keys[i] = to_key(prow[i]);
    __syncthreads();

    for (int p = 0; p < 4; p++) {
        int shift = 24 - 8 * p;
        hist[tid] = 0;
        __syncthreads();
        unsigned pref = s_prefix;
        for (int i = tid; i < D_HID; i += 256) {
            unsigned k = keys[i];
            bool ok = (p == 0) || ((k >> (shift + 8)) == pref);
            unsigned bin = (k >> shift) & 255u;
            unsigned active = __ballot_sync(0xFFFFFFFFu, ok);
            if (ok) {
                unsigned same = __match_any_sync(active, bin);
                int leader = __ffs(same) - 1;
                if ((tid & 31) == leader) atomicAdd(&hist[bin], __popc(same));
            }
        }
        __syncthreads();
        if (tid == 0) {
            int want = s_remaining;
            int cum = 0, b = 255;
            for (; b >= 0; b--) { cum += (int)hist[b]; if (cum >= want) break; }
            s_remaining = want - (cum - (int)hist[b]);
            s_prefix = (s_prefix << 8) | (unsigned)b;
        }
        __syncthreads();
    }

    const unsigned kth = s_prefix;

    for (int i = tid; i < D_HID; i += 256) {
        if (keys[i] > kth) {
            int p = atomicAdd(&s_cnt, 1);
            if (p < NCAND) cand[p] = i;
        }
    }
    __syncthreads();
    for (int i = tid; i < D_HID; i += 256) {
        if (keys[i] == kth) {
            int p = atomicAdd(&s_ecnt, 1) + s_cnt;
            if (p < NCAND) cand[p] = i;
        }
    }
    __syncthreads();
    if (tid == 0) {
        int c = s_cnt + s_ecnt;
        g_ccnt[row] = c < NCAND ? c : NCAND;
    }
}

// -------------------- K5: reference-bitwise refine {512,256} ------------------------------
// ref pre_acts = asc FMA chain [0,512), flush, asc FMA chain [512,768), add, + latent_bias.
__global__ __launch_bounds__(128)
void refine_kernel(const float* __restrict__ X,
                   const float* __restrict__ W,
                   const float* __restrict__ latent_bias,
                   float* __restrict__ hOut,
                   float* __restrict__ fOut,
                   float* __restrict__ idxOut) {
    __shared__ float xs[D_IN];
    __shared__ unsigned long long sk[NCAND];
    __shared__ float s_sumsq, s_rn;

    const int tid = threadIdx.x;
    const int row = blockIdx.x;
    const int lane = tid & 31;
    const int C = g_ccnt[row];
    const int* cand = g_cand + (size_t)row * NCAND;

    if (tid == 0) s_sumsq = 0.f;
    for (int i = tid; i < D_IN; i += 128) xs[i] = X[(size_t)row * D_IN + i];
    sk[tid] = 0ULL;
    __syncthreads();

    if (tid < C) {
        const int idx = cand[tid];
        const float* wrow = W + (size_t)idx * D_IN;

        float c1 = 0.f;
        #pragma unroll 2
        for (int k = 0; k < 512; k += 4) {
            float4 wv = *(const float4*)&wrow[k];
            c1 = __fmaf_rn(xs[k + 0], wv.x, c1);
            c1 = __fmaf_rn(xs[k + 1], wv.y, c1);
            c1 = __fmaf_rn(xs[k + 2], wv.z, c1);
            c1 = __fmaf_rn(xs[k + 3], wv.w, c1);
        }
        float c2 = 0.f;
        #pragma unroll 2
        for (int k = 512; k < 768; k += 4) {
            float4 wv = *(const float4*)&wrow[k];
            c2 = __fmaf_rn(xs[k + 0], wv.x, c2);
            c2 = __fmaf_rn(xs[k + 1], wv.y, c2);
            c2 = __fmaf_rn(xs[k + 2], wv.z, c2);
            c2 = __fmaf_rn(xs[k + 3], wv.w, c2);
        }
        float v = __fadd_rn(__fadd_rn(c1, c2), latent_bias[idx]);
        sk[tid] = ((unsigned long long)to_key(v) << 32) |
                  (unsigned long long)(0xFFFFFFFFu - (unsigned)idx);
    }
    __syncthreads();

    // bitonic sort 128 desc by (value desc, index asc)
    for (int size = 2; size <= NCAND; size <<= 1) {
        for (int stride = size >> 1; stride > 0; stride >>= 1) {
            int partner = tid ^ stride;
            if (partner > tid) {
                bool desc = ((tid & size) == 0);
                unsigned long long a = sk[tid], b = sk[partner];
                bool sw = desc ? (a < b) : (a > b);
                if (sw) { sk[tid] = b; sk[partner] = a; }
            }
            __syncthreads();
        }
    }

    float rv = 0.f; int idx = 0;
    if (tid < TOPK_K) {
        unsigned long long s = sk[tid];
        idx = (int)(0xFFFFFFFFu - (unsigned)(s & 0xFFFFFFFFull));
        float v = from_key((unsigned)(s >> 32));
        rv = fmaxf(v, 0.f);
        float v2 = rv * rv;
        #pragma unroll
        for (int o = 16; o; o >>= 1) v2 += __shfl_down_sync(0xFFFFFFFFu, v2, o);
        if (lane == 0) atomicAdd(&s_sumsq, v2);
    }
    __syncthreads();
    if (tid == 0) {
        float m = __fadd_rn(s_sumsq / (float)D_HID, 1e-8f);
        s_rn = __fdiv_rn(1.0f, __fsqrt_rn(m));
    }
    __syncthreads();

    if (tid < TOPK_K) {
        float fv = rv * s_rn;
        size_t so = (size_t)row * TOPK_K + tid;
        idxOut[so] = (float)idx;
        g_tv[so] = fv;
        g_tix[so] = idx;
        size_t ho = (size_t)row * D_HID + idx;
        hOut[ho] = rv;
        fOut[ho] = fv;
    }
}

// -------------------- K4: sparse decode --------------------
__global__ __launch_bounds__(192)
void decode_kernel(const float* __restrict__ X,
                   const float* __restrict__ pre_bias,
                   float* __restrict__ out) {
    __shared__ float fv[TOPK_K];
    __shared__ int fx[TOPK_K];
    const int row = blockIdx.x;
    const int tid = threadIdx.x;
    if (tid < TOPK_K) {
        fv[tid] = g_tv[(size_t)row * TOPK_K + tid];
        fx[tid] = g_tix[(size_t)row * TOPK_K + tid];
    }
    __syncthreads();

    const int d = tid * 4;
    float4 acc = *(const float4*)&pre_bias[d];
    #pragma unroll 8
    for (int k = 0; k < TOPK_K; k++) {
        float c = fv[k];
        const float4 w = *(const float4*)&g_WdT[(size_t)fx[k] * D_IN + d];
        acc.x += c * w.x; acc.y += c * w.y;
        acc.z += c * w.z; acc.w += c * w.w;
    }
    float4 xv = *(const float4*)&X[(size_t)row * D_IN + d];
    float4 r = make_float4(xv.x - acc.x, xv.y - acc.y, xv.z - acc.z, xv.w - acc.w);
    *(float4*)&out[XHAT_OFF + (size_t)row * D_IN + d] = acc;
    *(float4*)&out[RES_OFF  + (size_t)row * D_IN + d] = r;
}

// -------------------- launch --------------------
extern "C" void kernel_launch(void* const* d_in, const int* in_sizes, int n_in,
                              void* d_out, int out_size) {
    const float* x           = (const float*)d_in[0];
    const float* W_enc       = (const float*)d_in[1];
    const float* W_dec       = (const float*)d_in[2];
    const float* pre_bias    = (const float*)d_in[3];
    const float* latent_bias = (const float*)d_in[4];
    float* out = (float*)d_out;

    static bool attr_set = false;
    if (!attr_set) {
        cudaFuncSetAttribute(topk_select_kernel, cudaFuncAttributeMaxDynamicSharedMemorySize,
                             D_HID * (int)sizeof(unsigned));
        attr_set = true;
    }

    transpose_kernel<<<dim3(D_HID / 32, D_IN / 32), dim3(32, 8)>>>(W_dec);

    gemm_enc_kernel<<<dim3(D_HID / BN, B_ROWS / BM), 256>>>(
        x, W_enc, pre_bias, latent_bias, out + PRE_OFF);

    {
        long long n4 = (2LL * B_ROWS * D_HID) / 4;
        zero_kernel<<<8192, 256>>>((float4*)(out + H_OFF), n4);
    }

    topk_select_kernel<<<B_ROWS, 256, D_HID * sizeof(unsigned)>>>(out + PRE_OFF);

    refine_kernel<<<B_ROWS, 128>>>(x, W_enc, latent_bias,
        out + H_OFF, out + F_OFF, out + IDX_OFF);

    decode_kernel<<<B_ROWS, 192>>>(x, pre_bias, out);
}

// round 12
// speedup vs baseline: 1.7810x; 1.7810x over previous
#include <cuda_runtime.h>
#include <cuda_bf16.h>
#include <cstdint>

// Problem constants
#define B_ROWS   8192
#define D_IN     768
#define D_HID    12288
#define TOPK_K   64
#define NCAND    128
#define WANT     96

// Output layout (floats): x_hat, residual, h, f, indices, pre_acts
#define XHAT_OFF 0LL
#define RES_OFF  6291456LL
#define H_OFF    12582912LL
#define F_OFF    113246208LL
#define IDX_OFF  213909504LL
#define PRE_OFF  214433792LL

// -------------------- device scratch --------------------
__device__ float g_WdT[(size_t)D_HID * D_IN];
__device__ float g_tv[(size_t)B_ROWS * TOPK_K];
__device__ int   g_tix[(size_t)B_ROWS * TOPK_K];
__device__ int   g_cand[(size_t)B_ROWS * NCAND];
__device__ int   g_ccnt[B_ROWS];
// bf16 split operands for tensor-core encode GEMM
__device__ __nv_bfloat16 g_Xhi[(size_t)B_ROWS * D_IN];
__device__ __nv_bfloat16 g_Xlo[(size_t)B_ROWS * D_IN];
__device__ __nv_bfloat16 g_Whi[(size_t)D_HID * D_IN];
__device__ __nv_bfloat16 g_Wlo[(size_t)D_HID * D_IN];

// -------------------- K0a: bf16 split conversions --------------------
__global__ void convertX_kernel(const float* __restrict__ x,
                                const float* __restrict__ pre_bias) {
    const int row = blockIdx.x;
    for (int c = threadIdx.x; c < D_IN; c += 256) {
        float v = x[(size_t)row * D_IN + c] - pre_bias[c];
        __nv_bfloat16 hi = __float2bfloat16(v);
        float lo = v - __bfloat162float(hi);
        size_t o = (size_t)row * D_IN + c;
        g_Xhi[o] = hi;
        g_Xlo[o] = __float2bfloat16(lo);
    }
}

__global__ void convertW_kernel(const float* __restrict__ w) {
    const int row = blockIdx.x;
    for (int c = threadIdx.x; c < D_IN; c += 256) {
        float v = w[(size_t)row * D_IN + c];
        __nv_bfloat16 hi = __float2bfloat16(v);
        float lo = v - __bfloat162float(hi);
        size_t o = (size_t)row * D_IN + c;
        g_Whi[o] = hi;
        g_Wlo[o] = __float2bfloat16(lo);
    }
}

// -------------------- K0b: transpose W_dec -> g_WdT --------------------
__global__ void transpose_kernel(const float* __restrict__ Wd) {
    __shared__ float tile[32][33];
    int x = blockIdx.x * 32 + threadIdx.x;
    int y = blockIdx.y * 32 + threadIdx.y;
    #pragma unroll
    for (int i = 0; i < 32; i += 8)
        tile[threadIdx.y + i][threadIdx.x] = Wd[(size_t)(y + i) * D_HID + x];
    __syncthreads();
    int xo = blockIdx.y * 32 + threadIdx.x;
    int yo = blockIdx.x * 32 + threadIdx.y;
    #pragma unroll
    for (int i = 0; i < 32; i += 8)
        g_WdT[(size_t)(yo + i) * D_IN + xo] = tile[threadIdx.x][threadIdx.y + i];
}

// -------------------- K1: tensor-core encode GEMM (bf16 triple-split) --------------------
// pre_acts ~= (x - pre_bias) @ W_enc^T + latent_bias, error ~3e-6 abs.
// CTA tile 128x128, 8 warps of 64x32, K-chunks of 32, mma.sync m16n8k16 bf16->fp32.
#define SM_STRIDE 40   // padded row stride in bf16 elements (80B -> conflict-free frag loads)

__device__ __forceinline__ void mma16816(float* c, const unsigned* a, const unsigned* b) {
    asm volatile(
        "mma.sync.aligned.m16n8k16.row.col.f32.bf16.bf16.f32 "
        "{%0,%1,%2,%3}, {%4,%5,%6,%7}, {%8,%9}, {%0,%1,%2,%3};"
        : "+f"(c[0]), "+f"(c[1]), "+f"(c[2]), "+f"(c[3])
        : "r"(a[0]), "r"(a[1]), "r"(a[2]), "r"(a[3]), "r"(b[0]), "r"(b[1]));
}

__global__ __launch_bounds__(256, 2)
void gemm_mma_kernel(const float* __restrict__ latent_bias,
                     float* __restrict__ out) {
    extern __shared__ __nv_bfloat16 sm[];
    __nv_bfloat16* Ah = sm;
    __nv_bfloat16* Al = sm + 128 * SM_STRIDE;
    __nv_bfloat16* Bh = sm + 2 * 128 * SM_STRIDE;
    __nv_bfloat16* Bl = sm + 3 * 128 * SM_STRIDE;

    const int tid = threadIdx.x;
    const int warp = tid >> 5, lane = tid & 31;
    const int g = lane >> 2, tig = lane & 3;
    const int wm = warp >> 2, wn = warp & 3;     // 2 x 4 warp grid
    const int bm = blockIdx.y * 128;
    const int bn = blockIdx.x * 128;

    float acc[4][4][4];
    #pragma unroll
    for (int mt = 0; mt < 4; mt++)
        #pragma unroll
        for (int nt = 0; nt < 4; nt++)
            #pragma unroll
            for (int q = 0; q < 4; q++) acc[mt][nt][q] = 0.f;

    #pragma unroll 1
    for (int kc = 0; kc < D_IN; kc += 32) {
        // stage chunk: A(hi,lo) 128x32, B(hi,lo) 128x32
        #pragma unroll
        for (int t = 0; t < 2; t++) {
            int i = tid + t * 256;         // 0..511
            int r = i >> 2, c = i & 3;     // row, 16B-quad within 32 bf16
            size_t ga = (size_t)(bm + r) * D_IN + kc + c * 8;
            size_t gb = (size_t)(bn + r) * D_IN + kc + c * 8;
            int so = r * SM_STRIDE + c * 8;
            *(uint4*)&Ah[so] = *(const uint4*)&g_Xhi[ga];
            *(uint4*)&Al[so] = *(const uint4*)&g_Xlo[ga];
            *(uint4*)&Bh[so] = *(const uint4*)&g_Whi[gb];
            *(uint4*)&Bl[so] = *(const uint4*)&g_Wlo[gb];
        }
        __syncthreads();

        #pragma unroll
        for (int kk = 0; kk < 32; kk += 16) {
            unsigned bh[4][2], bl[4][2];
            #pragma unroll
            for (int nt = 0; nt < 4; nt++) {
                int n = wn * 32 + nt * 8 + g;
                int base = n * SM_STRIDE + kk + 2 * tig;
                bh[nt][0] = *(const unsigned*)&Bh[base];
                bh[nt][1] = *(const unsigned*)&Bh[base + 8];
                bl[nt][0] = *(const unsigned*)&Bl[base];
                bl[nt][1] = *(const unsigned*)&Bl[base + 8];
            }
            #pragma unroll
            for (int mt = 0; mt < 4; mt++) {
                int m = wm * 64 + mt * 16 + g;
                int base = m * SM_STRIDE + kk + 2 * tig;
                unsigned ah[4], al[4];
                ah[0] = *(const unsigned*)&Ah[base];
                ah[1] = *(const unsigned*)&Ah[base + 8 * SM_STRIDE];
                ah[2] = *(const unsigned*)&Ah[base + 8];
                ah[3] = *(const unsigned*)&Ah[base + 8 * SM_STRIDE + 8];
                al[0] = *(const unsigned*)&Al[base];
                al[1] = *(const unsigned*)&Al[base + 8 * SM_STRIDE];
                al[2] = *(const unsigned*)&Al[base + 8];
                al[3] = *(const unsigned*)&Al[base + 8 * SM_STRIDE + 8];
                #pragma unroll
                for (int nt = 0; nt < 4; nt++) {
                    mma16816(acc[mt][nt], ah, bh[nt]);   // hi*hi
                    mma16816(acc[mt][nt], ah, bl[nt]);   // hi*lo
                    mma16816(acc[mt][nt], al, bh[nt]);   // lo*hi
                }
            }
        }
        __syncthreads();
    }

    // epilogue: + latent_bias, store
    #pragma unroll
    for (int nt = 0; nt < 4; nt++) {
        int col = bn + wn * 32 + nt * 8 + 2 * tig;
        float lb0 = latent_bias[col], lb1 = latent_bias[col + 1];
        #pragma unroll
        for (int mt = 0; mt < 4; mt++) {
            int row = bm + wm * 64 + mt * 16 + g;
            float2 v0 = make_float2(acc[mt][nt][0] + lb0, acc[mt][nt][1] + lb1);
            float2 v1 = make_float2(acc[mt][nt][2] + lb0, acc[mt][nt][3] + lb1);
            *(float2*)&out[(size_t)row * D_HID + col] = v0;
            *(float2*)&out[(size_t)(row + 8) * D_HID + col] = v1;
        }
    }
}

// -------------------- K2: zero h and f regions --------------------
__global__ void zero_kernel(float4* __restrict__ p, long long n4) {
    long long i = (long long)blockIdx.x * blockDim.x + threadIdx.x;
    long long stride = (long long)gridDim.x * blockDim.x;
    float4 z = make_float4(0.f, 0.f, 0.f, 0.f);
    for (; i < n4; i += stride) p[i] = z;
}

// -------------------- key transforms --------------------
__device__ __forceinline__ unsigned to_key(float f) {
    unsigned u = __float_as_uint(f);
    return u ^ (((unsigned)((int)u >> 31)) | 0x80000000u);
}
__device__ __forceinline__ float from_key(unsigned k) {
    unsigned u = (k & 0x80000000u) ? (k ^ 0x80000000u) : ~k;
    return __uint_as_float(u);
}

// -------------------- K3: per-row top-96 candidate radix select --------------------
__global__ __launch_bounds__(256)
void topk_select_kernel(const float* __restrict__ pre) {
    extern __shared__ unsigned keys[];
    __shared__ unsigned hist[256];
    __shared__ unsigned s_prefix;
    __shared__ int s_remaining, s_cnt, s_ecnt;

    const int tid = threadIdx.x;
    const int row = blockIdx.x;
    const float* prow = pre + (size_t)row * D_HID;
    int* cand = g_cand + (size_t)row * NCAND;

    if (tid == 0) { s_prefix = 0u; s_remaining = WANT; s_cnt = 0; s_ecnt = 0; }
    for (int i = tid; i < D_HID; i += 256) keys[i] = to_key(prow[i]);
    __syncthreads();

    for (int p = 0; p < 4; p++) {
        int shift = 24 - 8 * p;
        hist[tid] = 0;
        __syncthreads();
        unsigned pref = s_prefix;
        for (int i = tid; i < D_HID; i += 256) {
            unsigned k = keys[i];
            bool ok = (p == 0) || ((k >> (shift + 8)) == pref);
            unsigned bin = (k >> shift) & 255u;
            unsigned active = __ballot_sync(0xFFFFFFFFu, ok);
            if (ok) {
                unsigned same = __match_any_sync(active, bin);
                int leader = __ffs(same) - 1;
                if ((tid & 31) == leader) atomicAdd(&hist[bin], __popc(same));
            }
        }
        __syncthreads();
        if (tid == 0) {
            int want = s_remaining;
            int cum = 0, b = 255;
            for (; b >= 0; b--) { cum += (int)hist[b]; if (cum >= want) break; }
            s_remaining = want - (cum - (int)hist[b]);
            s_prefix = (s_prefix << 8) | (unsigned)b;
        }
        __syncthreads();
    }

    const unsigned kth = s_prefix;

    for (int i = tid; i < D_HID; i += 256) {
        if (keys[i] > kth) {
            int p = atomicAdd(&s_cnt, 1);
            if (p < NCAND) cand[p] = i;
        }
    }
    __syncthreads();
    for (int i = tid; i < D_HID; i += 256) {
        if (keys[i] == kth) {
            int p = atomicAdd(&s_ecnt, 1) + s_cnt;
            if (p < NCAND) cand[p] = i;
        }
    }
    __syncthreads();
    if (tid == 0) {
        int c = s_cnt + s_ecnt;
        g_ccnt[row] = c < NCAND ? c : NCAND;
    }
}

// -------------------- K5: reference-bitwise refine {512,256} ------------------------------
__global__ __launch_bounds__(128)
void refine_kernel(const float* __restrict__ X,
                   const float* __restrict__ W,
                   const float* __restrict__ latent_bias,
                   float* __restrict__ hOut,
                   float* __restrict__ fOut,
                   float* __restrict__ idxOut) {
    __shared__ float xs[D_IN];
    __shared__ unsigned long long sk[NCAND];
    __shared__ float s_sumsq, s_rn;

    const int tid = threadIdx.x;
    const int row = blockIdx.x;
    const int lane = tid & 31;
    const int C = g_ccnt[row];
    const int* cand = g_cand + (size_t)row * NCAND;

    if (tid == 0) s_sumsq = 0.f;
    for (int i = tid; i < D_IN; i += 128) xs[i] = X[(size_t)row * D_IN + i];
    sk[tid] = 0ULL;
    __syncthreads();

    if (tid < C) {
        const int idx = cand[tid];
        const float* wrow = W + (size_t)idx * D_IN;

        float c1 = 0.f;
        #pragma unroll 2
        for (int k = 0; k < 512; k += 4) {
            float4 wv = *(const float4*)&wrow[k];
            c1 = __fmaf_rn(xs[k + 0], wv.x, c1);
            c1 = __fmaf_rn(xs[k + 1], wv.y, c1);
            c1 = __fmaf_rn(xs[k + 2], wv.z, c1);
            c1 = __fmaf_rn(xs[k + 3], wv.w, c1);
        }
        float c2 = 0.f;
        #pragma unroll 2
        for (int k = 512; k < 768; k += 4) {
            float4 wv = *(const float4*)&wrow[k];
            c2 = __fmaf_rn(xs[k + 0], wv.x, c2);
            c2 = __fmaf_rn(xs[k + 1], wv.y, c2);
            c2 = __fmaf_rn(xs[k + 2], wv.z, c2);
            c2 = __fmaf_rn(xs[k + 3], wv.w, c2);
        }
        float v = __fadd_rn(__fadd_rn(c1, c2), latent_bias[idx]);
        sk[tid] = ((unsigned long long)to_key(v) << 32) |
                  (unsigned long long)(0xFFFFFFFFu - (unsigned)idx);
    }
    __syncthreads();

    for (int size = 2; size <= NCAND; size <<= 1) {
        for (int stride = size >> 1; stride > 0; stride >>= 1) {
            int partner = tid ^ stride;
            if (partner > tid) {
                bool desc = ((tid & size) == 0);
                unsigned long long a = sk[tid], b = sk[partner];
                bool sw = desc ? (a < b) : (a > b);
                if (sw) { sk[tid] = b; sk[partner] = a; }
            }
            __syncthreads();
        }
    }

    float rv = 0.f; int idx = 0;
    if (tid < TOPK_K) {
        unsigned long long s = sk[tid];
        idx = (int)(0xFFFFFFFFu - (unsigned)(s & 0xFFFFFFFFull));
        float v = from_key((unsigned)(s >> 32));
        rv = fmaxf(v, 0.f);
        float v2 = rv * rv;
        #pragma unroll
        for (int o = 16; o; o >>= 1) v2 += __shfl_down_sync(0xFFFFFFFFu, v2, o);
        if (lane == 0) atomicAdd(&s_sumsq, v2);
    }
    __syncthreads();
    if (tid == 0) {
        float m = __fadd_rn(s_sumsq / (float)D_HID, 1e-8f);
        s_rn = __fdiv_rn(1.0f, __fsqrt_rn(m));
    }
    __syncthreads();

    if (tid < TOPK_K) {
        float fv = rv * s_rn;
        size_t so = (size_t)row * TOPK_K + tid;
        idxOut[so] = (float)idx;
        g_tv[so] = fv;
        g_tix[so] = idx;
        size_t ho = (size_t)row * D_HID + idx;
        hOut[ho] = rv;
        fOut[ho] = fv;
    }
}

// -------------------- K4: sparse decode --------------------
__global__ __launch_bounds__(192)
void decode_kernel(const float* __restrict__ X,
                   const float* __restrict__ pre_bias,
                   float* __restrict__ out) {
    __shared__ float fv[TOPK_K];
    __shared__ int fx[TOPK_K];
    const int row = blockIdx.x;
    const int tid = threadIdx.x;
    if (tid < TOPK_K) {
        fv[tid] = g_tv[(size_t)row * TOPK_K + tid];
        fx[tid] = g_tix[(size_t)row * TOPK_K + tid];
    }
    __syncthreads();

    const int d = tid * 4;
    float4 acc = *(const float4*)&pre_bias[d];
    #pragma unroll 8
    for (int k = 0; k < TOPK_K; k++) {
        float c = fv[k];
        const float4 w = *(const float4*)&g_WdT[(size_t)fx[k] * D_IN + d];
        acc.x += c * w.x; acc.y += c * w.y;
        acc.z += c * w.z; acc.w += c * w.w;
    }
    float4 xv = *(const float4*)&X[(size_t)row * D_IN + d];
    float4 r = make_float4(xv.x - acc.x, xv.y - acc.y, xv.z - acc.z, xv.w - acc.w);
    *(float4*)&out[XHAT_OFF + (size_t)row * D_IN + d] = acc;
    *(float4*)&out[RES_OFF  + (size_t)row * D_IN + d] = r;
}

// -------------------- launch --------------------
extern "C" void kernel_launch(void* const* d_in, const int* in_sizes, int n_in,
                              void* d_out, int out_size) {
    const float* x           = (const float*)d_in[0];
    const float* W_enc       = (const float*)d_in[1];
    const float* W_dec       = (const float*)d_in[2];
    const float* pre_bias    = (const float*)d_in[3];
    const float* latent_bias = (const float*)d_in[4];
    float* out = (float*)d_out;

    static bool attr_set = false;
    if (!attr_set) {
        cudaFuncSetAttribute(topk_select_kernel, cudaFuncAttributeMaxDynamicSharedMemorySize,
                             D_HID * (int)sizeof(unsigned));
        cudaFuncSetAttribute(gemm_mma_kernel, cudaFuncAttributeMaxDynamicSharedMemorySize,
                             4 * 128 * SM_STRIDE * (int)sizeof(__nv_bfloat16));
        attr_set = true;
    }

    // bf16 split conversions + W_dec transpose
    convertX_kernel<<<B_ROWS, 256>>>(x, pre_bias);
    convertW_kernel<<<D_HID, 256>>>(W_enc);
    transpose_kernel<<<dim3(D_HID / 32, D_IN / 32), dim3(32, 8)>>>(W_dec);

    // tensor-core encode GEMM -> pre_acts
    gemm_mma_kernel<<<dim3(D_HID / 128, B_ROWS / 128), 256,
                      4 * 128 * SM_STRIDE * sizeof(__nv_bfloat16)>>>(
        latent_bias, out + PRE_OFF);

    // zero h and f
    {
        long long n4 = (2LL * B_ROWS * D_HID) / 4;
        zero_kernel<<<8192, 256>>>((float4*)(out + H_OFF), n4);
    }

    topk_select_kernel<<<B_ROWS, 256, D_HID * sizeof(unsigned)>>>(out + PRE_OFF);

    refine_kernel<<<B_ROWS, 128>>>(x, W_enc, latent_bias,
        out + H_OFF, out + F_OFF, out + IDX_OFF);

    decode_kernel<<<B_ROWS, 192>>>(x, pre_bias, out);
}

// round 14
// speedup vs baseline: 2.0067x; 1.1267x over previous
#include <cuda_runtime.h>
#include <cuda_bf16.h>
#include <cstdint>

// Problem constants
#define B_ROWS   8192
#define D_IN     768
#define D_HID    12288
#define TOPK_K   64
#define NCAND    128
#define WANT     96

// Output layout (floats): x_hat, residual, h, f, indices, pre_acts
#define XHAT_OFF 0LL
#define RES_OFF  6291456LL
#define H_OFF    12582912LL
#define F_OFF    113246208LL
#define IDX_OFF  213909504LL
#define PRE_OFF  214433792LL

// -------------------- device scratch --------------------
__device__ float g_WdT[(size_t)D_HID * D_IN];
__device__ float g_tv[(size_t)B_ROWS * TOPK_K];
__device__ int   g_tix[(size_t)B_ROWS * TOPK_K];
__device__ int   g_cand[(size_t)B_ROWS * NCAND];
__device__ int   g_ccnt[B_ROWS];
// bf16 split operands for tensor-core encode GEMM
__device__ __nv_bfloat16 g_Xhi[(size_t)B_ROWS * D_IN];
__device__ __nv_bfloat16 g_Xlo[(size_t)B_ROWS * D_IN];
__device__ __nv_bfloat16 g_Whi[(size_t)D_HID * D_IN];
__device__ __nv_bfloat16 g_Wlo[(size_t)D_HID * D_IN];

// -------------------- helpers --------------------
__device__ __forceinline__ uint32_t smem_u32(const void* p) {
    uint32_t a;
    asm("{ .reg .u64 t; cvta.to.shared.u64 t, %1; cvt.u32.u64 %0, t; }" : "=r"(a) : "l"(p));
    return a;
}
#define CP16(dst, src) \
    asm volatile("cp.async.cg.shared.global [%0], [%1], 16;" :: "r"(dst), "l"(src) : "memory")
#define CP_COMMIT() asm volatile("cp.async.commit_group;" ::: "memory")

__device__ __forceinline__ void ldsm_x4(unsigned* r, uint32_t addr) {
    asm volatile("ldmatrix.sync.aligned.m8n8.x4.shared.b16 {%0,%1,%2,%3}, [%4];"
                 : "=r"(r[0]), "=r"(r[1]), "=r"(r[2]), "=r"(r[3]) : "r"(addr));
}
__device__ __forceinline__ void mma16816(float* c, const unsigned* a, const unsigned* b) {
    asm volatile(
        "mma.sync.aligned.m16n8k16.row.col.f32.bf16.bf16.f32 "
        "{%0,%1,%2,%3}, {%4,%5,%6,%7}, {%8,%9}, {%0,%1,%2,%3};"
        : "+f"(c[0]), "+f"(c[1]), "+f"(c[2]), "+f"(c[3])
        : "r"(a[0]), "r"(a[1]), "r"(a[2]), "r"(a[3]), "r"(b[0]), "r"(b[1]));
}

// -------------------- K0a: bf16 split conversions --------------------
__global__ void convertX_kernel(const float* __restrict__ x,
                                const float* __restrict__ pre_bias) {
    const int row = blockIdx.x;
    for (int c = threadIdx.x; c < D_IN; c += 256) {
        float v = x[(size_t)row * D_IN + c] - pre_bias[c];
        __nv_bfloat16 hi = __float2bfloat16(v);
        float lo = v - __bfloat162float(hi);
        size_t o = (size_t)row * D_IN + c;
        g_Xhi[o] = hi;
        g_Xlo[o] = __float2bfloat16(lo);
    }
}
__global__ void convertW_kernel(const float* __restrict__ w) {
    const int row = blockIdx.x;
    for (int c = threadIdx.x; c < D_IN; c += 256) {
        float v = w[(size_t)row * D_IN + c];
        __nv_bfloat16 hi = __float2bfloat16(v);
        float lo = v - __bfloat162float(hi);
        size_t o = (size_t)row * D_IN + c;
        g_Whi[o] = hi;
        g_Wlo[o] = __float2bfloat16(lo);
    }
}

// -------------------- K0b: transpose W_dec -> g_WdT --------------------
__global__ void transpose_kernel(const float* __restrict__ Wd) {
    __shared__ float tile[32][33];
    int x = blockIdx.x * 32 + threadIdx.x;
    int y = blockIdx.y * 32 + threadIdx.y;
    #pragma unroll
    for (int i = 0; i < 32; i += 8)
        tile[threadIdx.y + i][threadIdx.x] = Wd[(size_t)(y + i) * D_HID + x];
    __syncthreads();
    int xo = blockIdx.y * 32 + threadIdx.x;
    int yo = blockIdx.x * 32 + threadIdx.y;
    #pragma unroll
    for (int i = 0; i < 32; i += 8)
        g_WdT[(size_t)(yo + i) * D_IN + xo] = tile[threadIdx.x][threadIdx.y + i];
}

// -------------------- K1: HMMA encode GEMM, ldmatrix + cp.async double buffer -------------
// CTA tile 128x128, 8 warps (2x4) of 64x32, K-chunks of 32, bf16 triple-split.
#define SMS    40        // padded row stride in bf16 (80 B)
#define ARR    10240     // bytes per 128-row array (128 * 80)
#define BUFB   40960     // Ah, Al, Bh, Bl
#define NCH    24        // 768 / 32

__global__ __launch_bounds__(256, 2)
void gemm_mma_kernel(const float* __restrict__ latent_bias,
                     float* __restrict__ out) {
    extern __shared__ char dsm[];
    float* sbias = (float*)dsm;
    const uint32_t bufs = smem_u32(dsm) + 1024;

    const int tid = threadIdx.x;
    const int warp = tid >> 5, lane = tid & 31;
    const int g = lane >> 2, tig = lane & 3;
    const int wm = warp >> 2, wn = warp & 3;
    const int bm = blockIdx.y * 128;
    const int bn = blockIdx.x * 128;

    if (tid < 128) sbias[tid] = latent_bias[bn + tid];

    float acc[4][4][4];
    #pragma unroll
    for (int mt = 0; mt < 4; mt++)
        #pragma unroll
        for (int nt = 0; nt < 4; nt++)
            #pragma unroll
            for (int q = 0; q < 4; q++) acc[mt][nt][q] = 0.f;

    // per-thread staging indices (2 x 16B rows per array)
    const int r0 = tid >> 1, q0 = (tid & 1) << 1;   // rows 0..127, quad pairs {0,1} or {2,3}

    auto stage = [&](int buf, int kc) {
        uint32_t b = bufs + buf * BUFB;
        #pragma unroll
        for (int t = 0; t < 2; t++) {
            int q = q0 + t;
            uint32_t dst = b + (uint32_t)(r0 * 80 + q * 16);
            size_t ga = (size_t)(bm + r0) * D_IN + kc + q * 8;
            size_t gb = (size_t)(bn + r0) * D_IN + kc + q * 8;
            CP16(dst, g_Xhi + ga);
            CP16(dst + ARR, g_Xlo + ga);
            CP16(dst + 2 * ARR, g_Whi + gb);
            CP16(dst + 3 * ARR, g_Wlo + gb);
        }
        CP_COMMIT();
    };

    // ldmatrix lane offsets (elements)
    const int a_r = lane & 15;
    const int a_c = (lane >> 4) << 3;
    const int b_r = (lane & 7) | ((lane >> 4) << 3);
    const int b_c = ((lane >> 3) & 1) << 3;

    stage(0, 0);
    #pragma unroll 1
    for (int c = 0; c < NCH; c++) {
        if (c + 1 < NCH) {
            stage((c + 1) & 1, (c + 1) * 32);
            asm volatile("cp.async.wait_group 1;" ::: "memory");
        } else {
            asm volatile("cp.async.wait_group 0;" ::: "memory");
        }
        __syncthreads();

        const uint32_t Ab = bufs + (c & 1) * BUFB;
        const uint32_t Bb = Ab + 2 * ARR;
        #pragma unroll
        for (int kk = 0; kk < 32; kk += 16) {
            unsigned bh[2][4], bl[2][4];
            #pragma unroll
            for (int ntp = 0; ntp < 2; ntp++) {
                uint32_t ba = Bb + (uint32_t)(((wn * 32 + ntp * 16 + b_r) * SMS + kk + b_c) * 2);
                ldsm_x4(bh[ntp], ba);
                ldsm_x4(bl[ntp], ba + ARR);
            }
            #pragma unroll
            for (int mt = 0; mt < 4; mt++) {
                uint32_t aa = Ab + (uint32_t)(((wm * 64 + mt * 16 + a_r) * SMS + kk + a_c) * 2);
                unsigned ah[4], al[4];
                ldsm_x4(ah, aa);
                ldsm_x4(al, aa + ARR);
                #pragma unroll
                for (int nt = 0; nt < 4; nt++) {
                    const unsigned* bhp = &bh[nt >> 1][(nt & 1) * 2];
                    const unsigned* blp = &bl[nt >> 1][(nt & 1) * 2];
                    mma16816(acc[mt][nt], ah, bhp);   // hi*hi
                    mma16816(acc[mt][nt], ah, blp);   // hi*lo
                    mma16816(acc[mt][nt], al, bhp);   // lo*hi
                }
            }
        }
        __syncthreads();
    }

    // epilogue: + latent_bias, store
    #pragma unroll
    for (int nt = 0; nt < 4; nt++) {
        int col = bn + wn * 32 + nt * 8 + 2 * tig;
        float lb0 = sbias[col - bn], lb1 = sbias[col - bn + 1];
        #pragma unroll
        for (int mt = 0; mt < 4; mt++) {
            int row = bm + wm * 64 + mt * 16 + g;
            float2 v0 = make_float2(acc[mt][nt][0] + lb0, acc[mt][nt][1] + lb1);
            float2 v1 = make_float2(acc[mt][nt][2] + lb0, acc[mt][nt][3] + lb1);
            *(float2*)&out[(size_t)row * D_HID + col] = v0;
            *(float2*)&out[(size_t)(row + 8) * D_HID + col] = v1;
        }
    }
}

// -------------------- K2: zero h and f regions --------------------
__global__ void zero_kernel(float4* __restrict__ p, long long n4) {
    long long i = (long long)blockIdx.x * blockDim.x + threadIdx.x;
    long long stride = (long long)gridDim.x * blockDim.x;
    float4 z = make_float4(0.f, 0.f, 0.f, 0.f);
    for (; i < n4; i += stride) p[i] = z;
}

// -------------------- key transforms --------------------
__device__ __forceinline__ unsigned to_key(float f) {
    unsigned u = __float_as_uint(f);
    return u ^ (((unsigned)((int)u >> 31)) | 0x80000000u);
}
__device__ __forceinline__ float from_key(unsigned k) {
    unsigned u = (k & 0x80000000u) ? (k ^ 0x80000000u) : ~k;
    return __uint_as_float(u);
}

// -------------------- K3: per-row top-~96 candidate select (2-pass radix) ----------------
__global__ __launch_bounds__(512)
void topk_select_kernel(const float* __restrict__ pre) {
    extern __shared__ unsigned keys[];    // 12288 keys (48 KB)
    __shared__ unsigned hist[256];
    __shared__ int s_b1, s_want2, s_prefix, s_cnt;

    const int tid = threadIdx.x;
    const int row = blockIdx.x;
    const float* prow = pre + (size_t)row * D_HID;
    int* cand = g_cand + (size_t)row * NCAND;

    if (tid == 0) s_cnt = 0;
    if (tid < 256) hist[tid] = 0;
    for (int i = tid; i < D_HID; i += 512) keys[i] = to_key(prow[i]);
    __syncthreads();

    // pass 1: bits [31:24], warp-aggregated histogram
    for (int i = tid; i < D_HID; i += 512) {
        unsigned bin = keys[i] >> 24;
        unsigned same = __match_any_sync(0xFFFFFFFFu, bin);
        int leader = __ffs(same) - 1;
        if ((tid & 31) == leader) atomicAdd(&hist[bin], __popc(same));
    }
    __syncthreads();
    if (tid == 0) {
        int cum = 0, b = 255;
        for (; b >= 0; b--) { cum += (int)hist[b]; if (cum >= WANT) break; }
        s_b1 = b;
        s_want2 = WANT - (cum - (int)hist[b]);
    }
    __syncthreads();
    const unsigned b1 = (unsigned)s_b1;
    if (tid < 256) hist[tid] = 0;
    __syncthreads();

    // pass 2: among top-byte == b1, histogram bits [23:16]
    for (int i = tid; i < D_HID; i += 512) {
        unsigned k = keys[i];
        if ((k >> 24) == b1) atomicAdd(&hist[(k >> 16) & 255u], 1u);
    }
    __syncthreads();
    if (tid == 0) {
        int want2 = s_want2;
        int cum = 0, b = 255;
        for (; b >= 0; b--) { cum += (int)hist[b]; if (cum >= want2) break; }
        s_prefix = (int)((b1 << 8) | (unsigned)b);
    }
    __syncthreads();
    const unsigned prefix = (unsigned)s_prefix;

    // collect: strictly greater 16-bit prefix first (count < WANT guaranteed)
    for (int i = tid; i < D_HID; i += 512) {
        if ((keys[i] >> 16) > prefix) {
            int p = atomicAdd(&s_cnt, 1);
            if (p < NCAND) cand[p] = i;
        }
    }
    __syncthreads();
    // boundary bin appended, capped
    for (int i = tid; i < D_HID; i += 512) {
        if ((keys[i] >> 16) == prefix) {
            int p = atomicAdd(&s_cnt, 1);
            if (p < NCAND) cand[p] = i;
        }
    }
    __syncthreads();
    if (tid == 0) g_ccnt[row] = s_cnt < NCAND ? s_cnt : NCAND;
}

// -------------------- K5: reference-bitwise refine {512,256} ------------------------------
__global__ __launch_bounds__(128)
void refine_kernel(const float* __restrict__ X,
                   const float* __restrict__ W,
                   const float* __restrict__ latent_bias,
                   float* __restrict__ hOut,
                   float* __restrict__ fOut,
                   float* __restrict__ idxOut) {
    __shared__ float xs[D_IN];
    __shared__ unsigned long long sk[NCAND];
    __shared__ float s_sumsq, s_rn;

    const int tid = threadIdx.x;
    const int row = blockIdx.x;
    const int lane = tid & 31;
    const int C = g_ccnt[row];
    const int* cand = g_cand + (size_t)row * NCAND;

    if (tid == 0) s_sumsq = 0.f;
    for (int i = tid; i < D_IN; i += 128) xs[i] = X[(size_t)row * D_IN + i];
    sk[tid] = 0ULL;
    __syncthreads();

    if (tid < C) {
        const int idx = cand[tid];
        const float* wrow = W + (size_t)idx * D_IN;

        float c1 = 0.f;
        #pragma unroll 2
        for (int k = 0; k < 512; k += 4) {
            float4 wv = *(const float4*)&wrow[k];
            c1 = __fmaf_rn(xs[k + 0], wv.x, c1);
            c1 = __fmaf_rn(xs[k + 1], wv.y, c1);
            c1 = __fmaf_rn(xs[k + 2], wv.z, c1);
            c1 = __fmaf_rn(xs[k + 3], wv.w, c1);
        }
        float c2 = 0.f;
        #pragma unroll 2
        for (int k = 512; k < 768; k += 4) {
            float4 wv = *(const float4*)&wrow[k];
            c2 = __fmaf_rn(xs[k + 0], wv.x, c2);
            c2 = __fmaf_rn(xs[k + 1], wv.y, c2);
            c2 = __fmaf_rn(xs[k + 2], wv.z, c2);
            c2 = __fmaf_rn(xs[k + 3], wv.w, c2);
        }
        float v = __fadd_rn(__fadd_rn(c1, c2), latent_bias[idx]);
        sk[tid] = ((unsigned long long)to_key(v) << 32) |
                  (unsigned long long)(0xFFFFFFFFu - (unsigned)idx);
    }
    __syncthreads();

    for (int size = 2; size <= NCAND; size <<= 1) {
        for (int stride = size >> 1; stride > 0; stride >>= 1) {
            int partner = tid ^ stride;
            if (partner > tid) {
                bool desc = ((tid & size) == 0);
                unsigned long long a = sk[tid], b = sk[partner];
                bool sw = desc ? (a < b) : (a > b);
                if (sw) { sk[tid] = b; sk[partner] = a; }
            }
            __syncthreads();
        }
    }

    float rv = 0.f; int idx = 0;
    if (tid < TOPK_K) {
        unsigned long long s = sk[tid];
        idx = (int)(0xFFFFFFFFu - (unsigned)(s & 0xFFFFFFFFull));
        float v = from_key((unsigned)(s >> 32));
        rv = fmaxf(v, 0.f);
        float v2 = rv * rv;
        #pragma unroll
        for (int o = 16; o; o >>= 1) v2 += __shfl_down_sync(0xFFFFFFFFu, v2, o);
        if (lane == 0) atomicAdd(&s_sumsq, v2);
    }
    __syncthreads();
    if (tid == 0) {
        float m = __fadd_rn(s_sumsq / (float)D_HID, 1e-8f);
        s_rn = __fdiv_rn(1.0f, __fsqrt_rn(m));
    }
    __syncthreads();

    if (tid < TOPK_K) {
        float fv = rv * s_rn;
        size_t so = (size_t)row * TOPK_K + tid;
        idxOut[so] = (float)idx;
        g_tv[so] = fv;
        g_tix[so] = idx;
        size_t ho = (size_t)row * D_HID + idx;
        hOut[ho] = rv;
        fOut[ho] = fv;
    }
}

// -------------------- K4: sparse decode --------------------
__global__ __launch_bounds__(192)
void decode_kernel(const float* __restrict__ X,
                   const float* __restrict__ pre_bias,
                   float* __restrict__ out) {
    __shared__ float fv[TOPK_K];
    __shared__ int fx[TOPK_K];
    const int row = blockIdx.x;
    const int tid = threadIdx.x;
    if (tid < TOPK_K) {
        fv[tid] = g_tv[(size_t)row * TOPK_K + tid];
        fx[tid] = g_tix[(size_t)row * TOPK_K + tid];
    }
    __syncthreads();

    const int d = tid * 4;
    float4 acc = *(const float4*)&pre_bias[d];
    #pragma unroll 8
    for (int k = 0; k < TOPK_K; k++) {
        float c = fv[k];
        const float4 w = *(const float4*)&g_WdT[(size_t)fx[k] * D_IN + d];
        acc.x += c * w.x; acc.y += c * w.y;
        acc.z += c * w.z; acc.w += c * w.w;
    }
    float4 xv = *(const float4*)&X[(size_t)row * D_IN + d];
    float4 r = make_float4(xv.x - acc.x, xv.y - acc.y, xv.z - acc.z, xv.w - acc.w);
    *(float4*)&out[XHAT_OFF + (size_t)row * D_IN + d] = acc;
    *(float4*)&out[RES_OFF  + (size_t)row * D_IN + d] = r;
}

// -------------------- launch --------------------
extern "C" void kernel_launch(void* const* d_in, const int* in_sizes, int n_in,
                              void* d_out, int out_size) {
    const float* x           = (const float*)d_in[0];
    const float* W_enc       = (const float*)d_in[1];
    const float* W_dec       = (const float*)d_in[2];
    const float* pre_bias    = (const float*)d_in[3];
    const float* latent_bias = (const float*)d_in[4];
    float* out = (float*)d_out;

    static bool attr_set = false;
    if (!attr_set) {
        cudaFuncSetAttribute(topk_select_kernel, cudaFuncAttributeMaxDynamicSharedMemorySize,
                             D_HID * (int)sizeof(unsigned));
        cudaFuncSetAttribute(gemm_mma_kernel, cudaFuncAttributeMaxDynamicSharedMemorySize,
                             1024 + 2 * BUFB);
        attr_set = true;
    }

    convertX_kernel<<<B_ROWS, 256>>>(x, pre_bias);
    convertW_kernel<<<D_HID, 256>>>(W_enc);
    transpose_kernel<<<dim3(D_HID / 32, D_IN / 32), dim3(32, 8)>>>(W_dec);

    gemm_mma_kernel<<<dim3(D_HID / 128, B_ROWS / 128), 256, 1024 + 2 * BUFB>>>(
        latent_bias, out + PRE_OFF);

    {
        long long n4 = (2LL * B_ROWS * D_HID) / 4;
        zero_kernel<<<8192, 256>>>((float4*)(out + H_OFF), n4);
    }

    topk_select_kernel<<<B_ROWS, 512, D_HID * sizeof(unsigned)>>>(out + PRE_OFF);

    refine_kernel<<<B_ROWS, 128>>>(x, W_enc, latent_bias,
        out + H_OFF, out + F_OFF, out + IDX_OFF);

    decode_kernel<<<B_ROWS, 192>>>(x, pre_bias, out);
}

// round 15
// speedup vs baseline: 2.0859x; 1.0395x over previous
#include <cuda_runtime.h>
#include <cuda_bf16.h>
#include <cstdint>

// Problem constants
#define B_ROWS   8192
#define D_IN     768
#define D_HID    12288
#define TOPK_K   64
#define NCAND    128
#define WANT     72

// Output layout (floats): x_hat, residual, h, f, indices, pre_acts
#define XHAT_OFF 0LL
#define RES_OFF  6291456LL
#define H_OFF    12582912LL
#define F_OFF    113246208LL
#define IDX_OFF  213909504LL
#define PRE_OFF  214433792LL

// -------------------- device scratch --------------------
__device__ float g_WdT[(size_t)D_HID * D_IN];
__device__ float g_tv[(size_t)B_ROWS * TOPK_K];
__device__ int   g_tix[(size_t)B_ROWS * TOPK_K];
__device__ int   g_cand[(size_t)B_ROWS * NCAND];
__device__ int   g_ccnt[B_ROWS];
// bf16 split operands for tensor-core encode GEMM
__device__ __nv_bfloat16 g_Xhi[(size_t)B_ROWS * D_IN];
__device__ __nv_bfloat16 g_Xlo[(size_t)B_ROWS * D_IN];
__device__ __nv_bfloat16 g_Whi[(size_t)D_HID * D_IN];
__device__ __nv_bfloat16 g_Wlo[(size_t)D_HID * D_IN];

// -------------------- helpers --------------------
__device__ __forceinline__ uint32_t smem_u32(const void* p) {
    uint32_t a;
    asm("{ .reg .u64 t; cvta.to.shared.u64 t, %1; cvt.u32.u64 %0, t; }" : "=r"(a) : "l"(p));
    return a;
}
#define CP16(dst, src) \
    asm volatile("cp.async.cg.shared.global [%0], [%1], 16;" :: "r"(dst), "l"(src) : "memory")
#define CP_COMMIT() asm volatile("cp.async.commit_group;" ::: "memory")

__device__ __forceinline__ void ldsm_x4(unsigned* r, uint32_t addr) {
    asm volatile("ldmatrix.sync.aligned.m8n8.x4.shared.b16 {%0,%1,%2,%3}, [%4];"
                 : "=r"(r[0]), "=r"(r[1]), "=r"(r[2]), "=r"(r[3]) : "r"(addr));
}
__device__ __forceinline__ void mma16816(float* c, const unsigned* a, const unsigned* b) {
    asm volatile(
        "mma.sync.aligned.m16n8k16.row.col.f32.bf16.bf16.f32 "
        "{%0,%1,%2,%3}, {%4,%5,%6,%7}, {%8,%9}, {%0,%1,%2,%3};"
        : "+f"(c[0]), "+f"(c[1]), "+f"(c[2]), "+f"(c[3])
        : "r"(a[0]), "r"(a[1]), "r"(a[2]), "r"(a[3]), "r"(b[0]), "r"(b[1]));
}

// -------------------- K0a: bf16 split conversions --------------------
__global__ void convertX_kernel(const float* __restrict__ x,
                                const float* __restrict__ pre_bias) {
    const int row = blockIdx.x;
    for (int c = threadIdx.x; c < D_IN; c += 256) {
        float v = x[(size_t)row * D_IN + c] - pre_bias[c];
        __nv_bfloat16 hi = __float2bfloat16(v);
        float lo = v - __bfloat162float(hi);
        size_t o = (size_t)row * D_IN + c;
        g_Xhi[o] = hi;
        g_Xlo[o] = __float2bfloat16(lo);
    }
}
__global__ void convertW_kernel(const float* __restrict__ w) {
    const int row = blockIdx.x;
    for (int c = threadIdx.x; c < D_IN; c += 256) {
        float v = w[(size_t)row * D_IN + c];
        __nv_bfloat16 hi = __float2bfloat16(v);
        float lo = v - __bfloat162float(hi);
        size_t o = (size_t)row * D_IN + c;
        g_Whi[o] = hi;
        g_Wlo[o] = __float2bfloat16(lo);
    }
}

// -------------------- K0b: transpose W_dec -> g_WdT --------------------
__global__ void transpose_kernel(const float* __restrict__ Wd) {
    __shared__ float tile[32][33];
    int x = blockIdx.x * 32 + threadIdx.x;
    int y = blockIdx.y * 32 + threadIdx.y;
    #pragma unroll
    for (int i = 0; i < 32; i += 8)
        tile[threadIdx.y + i][threadIdx.x] = Wd[(size_t)(y + i) * D_HID + x];
    __syncthreads();
    int xo = blockIdx.y * 32 + threadIdx.x;
    int yo = blockIdx.x * 32 + threadIdx.y;
    #pragma unroll
    for (int i = 0; i < 32; i += 8)
        g_WdT[(size_t)(yo + i) * D_IN + xo] = tile[threadIdx.x][threadIdx.y + i];
}

// -------------------- K1: HMMA encode GEMM, ldmatrix + cp.async double buffer -------------
#define SMS    40
#define ARR    10240
#define BUFB   40960
#define NCH    24

__global__ __launch_bounds__(256, 2)
void gemm_mma_kernel(const float* __restrict__ latent_bias,
                     float* __restrict__ out) {
    extern __shared__ char dsm[];
    float* sbias = (float*)dsm;
    const uint32_t bufs = smem_u32(dsm) + 1024;

    const int tid = threadIdx.x;
    const int warp = tid >> 5, lane = tid & 31;
    const int g = lane >> 2, tig = lane & 3;
    const int wm = warp >> 2, wn = warp & 3;
    const int bm = blockIdx.y * 128;
    const int bn = blockIdx.x * 128;

    if (tid < 128) sbias[tid] = latent_bias[bn + tid];

    float acc[4][4][4];
    #pragma unroll
    for (int mt = 0; mt < 4; mt++)
        #pragma unroll
        for (int nt = 0; nt < 4; nt++)
            #pragma unroll
            for (int q = 0; q < 4; q++) acc[mt][nt][q] = 0.f;

    const int r0 = tid >> 1, q0 = (tid & 1) << 1;

    auto stage = [&](int buf, int kc) {
        uint32_t b = bufs + buf * BUFB;
        #pragma unroll
        for (int t = 0; t < 2; t++) {
            int q = q0 + t;
            uint32_t dst = b + (uint32_t)(r0 * 80 + q * 16);
            size_t ga = (size_t)(bm + r0) * D_IN + kc + q * 8;
            size_t gb = (size_t)(bn + r0) * D_IN + kc + q * 8;
            CP16(dst, g_Xhi + ga);
            CP16(dst + ARR, g_Xlo + ga);
            CP16(dst + 2 * ARR, g_Whi + gb);
            CP16(dst + 3 * ARR, g_Wlo + gb);
        }
        CP_COMMIT();
    };

    const int a_r = lane & 15;
    const int a_c = (lane >> 4) << 3;
    const int b_r = (lane & 7) | ((lane >> 4) << 3);
    const int b_c = ((lane >> 3) & 1) << 3;

    stage(0, 0);
    #pragma unroll 1
    for (int c = 0; c < NCH; c++) {
        if (c + 1 < NCH) {
            stage((c + 1) & 1, (c + 1) * 32);
            asm volatile("cp.async.wait_group 1;" ::: "memory");
        } else {
            asm volatile("cp.async.wait_group 0;" ::: "memory");
        }
        __syncthreads();

        const uint32_t Ab = bufs + (c & 1) * BUFB;
        const uint32_t Bb = Ab + 2 * ARR;
        #pragma unroll
        for (int kk = 0; kk < 32; kk += 16) {
            unsigned bh[2][4], bl[2][4];
            #pragma unroll
            for (int ntp = 0; ntp < 2; ntp++) {
                uint32_t ba = Bb + (uint32_t)(((wn * 32 + ntp * 16 + b_r) * SMS + kk + b_c) * 2);
                ldsm_x4(bh[ntp], ba);
                ldsm_x4(bl[ntp], ba + ARR);
            }
            #pragma unroll
            for (int mt = 0; mt < 4; mt++) {
                uint32_t aa = Ab + (uint32_t)(((wm * 64 + mt * 16 + a_r) * SMS + kk + a_c) * 2);
                unsigned ah[4], al[4];
                ldsm_x4(ah, aa);
                ldsm_x4(al, aa + ARR);
                #pragma unroll
                for (int nt = 0; nt < 4; nt++) {
                    const unsigned* bhp = &bh[nt >> 1][(nt & 1) * 2];
                    const unsigned* blp = &bl[nt >> 1][(nt & 1) * 2];
                    mma16816(acc[mt][nt], ah, bhp);
                    mma16816(acc[mt][nt], ah, blp);
                    mma16816(acc[mt][nt], al, bhp);
                }
            }
        }
        __syncthreads();
    }

    #pragma unroll
    for (int nt = 0; nt < 4; nt++) {
        int col = bn + wn * 32 + nt * 8 + 2 * tig;
        float lb0 = sbias[col - bn], lb1 = sbias[col - bn + 1];
        #pragma unroll
        for (int mt = 0; mt < 4; mt++) {
            int row = bm + wm * 64 + mt * 16 + g;
            float2 v0 = make_float2(acc[mt][nt][0] + lb0, acc[mt][nt][1] + lb1);
            float2 v1 = make_float2(acc[mt][nt][2] + lb0, acc[mt][nt][3] + lb1);
            *(float2*)&out[(size_t)row * D_HID + col] = v0;
            *(float2*)&out[(size_t)(row + 8) * D_HID + col] = v1;
        }
    }
}

// -------------------- K2: zero h and f regions --------------------
__global__ void zero_kernel(float4* __restrict__ p, long long n4) {
    long long i = (long long)blockIdx.x * blockDim.x + threadIdx.x;
    long long stride = (long long)gridDim.x * blockDim.x;
    float4 z = make_float4(0.f, 0.f, 0.f, 0.f);
    for (; i < n4; i += stride) p[i] = z;
}

// -------------------- key transforms --------------------
__device__ __forceinline__ unsigned to_key(float f) {
    unsigned u = __float_as_uint(f);
    return u ^ (((unsigned)((int)u >> 31)) | 0x80000000u);
}
__device__ __forceinline__ float from_key(unsigned k) {
    unsigned u = (k & 0x80000000u) ? (k ^ 0x80000000u) : ~k;
    return __uint_as_float(u);
}

// -------------------- K3: per-row top-~72 candidate select (2-pass radix, fused load) ----
__global__ __launch_bounds__(512)
void topk_select_kernel(const float* __restrict__ pre) {
    extern __shared__ unsigned keys[];    // 12288 keys (48 KB)
    __shared__ unsigned hist[256];
    __shared__ int s_b1, s_want2, s_prefix, s_cnt;

    const int tid = threadIdx.x;
    const int row = blockIdx.x;
    const float* prow = pre + (size_t)row * D_HID;
    int* cand = g_cand + (size_t)row * NCAND;

    if (tid == 0) s_cnt = 0;
    if (tid < 256) hist[tid] = 0;
    __syncthreads();

    // fused: load keys + pass-1 histogram (bits [31:24])
    for (int i = tid; i < D_HID; i += 512) {
        unsigned k = to_key(prow[i]);
        keys[i] = k;
        unsigned bin = k >> 24;
        unsigned same = __match_any_sync(0xFFFFFFFFu, bin);
        int leader = __ffs(same) - 1;
        if ((tid & 31) == leader) atomicAdd(&hist[bin], __popc(same));
    }
    __syncthreads();
    if (tid == 0) {
        int cum = 0, b = 255;
        for (; b >= 0; b--) { cum += (int)hist[b]; if (cum >= WANT) break; }
        s_b1 = b;
        s_want2 = WANT - (cum - (int)hist[b]);
    }
    __syncthreads();
    const unsigned b1 = (unsigned)s_b1;
    if (tid < 256) hist[tid] = 0;
    __syncthreads();

    // pass 2: among top-byte == b1, histogram bits [23:16]
    for (int i = tid; i < D_HID; i += 512) {
        unsigned k = keys[i];
        if ((k >> 24) == b1) atomicAdd(&hist[(k >> 16) & 255u], 1u);
    }
    __syncthreads();
    if (tid == 0) {
        int want2 = s_want2;
        int cum = 0, b = 255;
        for (; b >= 0; b--) { cum += (int)hist[b]; if (cum >= want2) break; }
        s_prefix = (int)((b1 << 8) | (unsigned)b);
    }
    __syncthreads();
    const unsigned prefix = (unsigned)s_prefix;

    // collect: strictly greater 16-bit prefix first (count < WANT guaranteed)
    for (int i = tid; i < D_HID; i += 512) {
        if ((keys[i] >> 16) > prefix) {
            int p = atomicAdd(&s_cnt, 1);
            if (p < NCAND) cand[p] = i;
        }
    }
    __syncthreads();
    // boundary bin appended, capped
    for (int i = tid; i < D_HID; i += 512) {
        if ((keys[i] >> 16) == prefix) {
            int p = atomicAdd(&s_cnt, 1);
            if (p < NCAND) cand[p] = i;
        }
    }
    __syncthreads();
    if (tid == 0) g_ccnt[row] = s_cnt < NCAND ? s_cnt : NCAND;
}

// -------------------- K5: reference-bitwise refine {512,256}, warp-split chunks ----------
// Warps 0-3: chunk [0,512) chains for candidates 0..127 (warp w -> cand w*32+lane).
// Warps 4-7: chunk [512,768) chains. Combined (c1+c2)+bias preserves reference bits.
__global__ __launch_bounds__(256)
void refine_kernel(const float* __restrict__ X,
                   const float* __restrict__ W,
                   const float* __restrict__ latent_bias,
                   float* __restrict__ hOut,
                   float* __restrict__ fOut,
                   float* __restrict__ idxOut) {
    __shared__ float xs[D_IN];
    __shared__ float sC1[NCAND], sC2[NCAND];
    __shared__ unsigned long long sk[NCAND];
    __shared__ float s_sumsq, s_rn;

    const int tid = threadIdx.x;
    const int row = blockIdx.x;
    const int warp = tid >> 5, lane = tid & 31;
    const int C = g_ccnt[row];
    const int* cand = g_cand + (size_t)row * NCAND;

    if (tid == 0) s_sumsq = 0.f;
    for (int i = tid; i < D_IN; i += 256) xs[i] = X[(size_t)row * D_IN + i];
    if (tid < NCAND) sk[tid] = 0ULL;
    __syncthreads();

    if (warp < 4) {
        const int c = warp * 32 + lane;
        if (c < C) {
            const float* wrow = W + (size_t)cand[c] * D_IN;
            float c1 = 0.f;
            #pragma unroll 2
            for (int k = 0; k < 512; k += 4) {
                float4 wv = *(const float4*)&wrow[k];
                c1 = __fmaf_rn(xs[k + 0], wv.x, c1);
                c1 = __fmaf_rn(xs[k + 1], wv.y, c1);
                c1 = __fmaf_rn(xs[k + 2], wv.z, c1);
                c1 = __fmaf_rn(xs[k + 3], wv.w, c1);
            }
            sC1[c] = c1;
        }
    } else {
        const int c = (warp - 4) * 32 + lane;
        if (c < C) {
            const float* wrow = W + (size_t)cand[c] * D_IN;
            float c2 = 0.f;
            #pragma unroll 2
            for (int k = 512; k < 768; k += 4) {
                float4 wv = *(const float4*)&wrow[k];
                c2 = __fmaf_rn(xs[k + 0], wv.x, c2);
                c2 = __fmaf_rn(xs[k + 1], wv.y, c2);
                c2 = __fmaf_rn(xs[k + 2], wv.z, c2);
                c2 = __fmaf_rn(xs[k + 3], wv.w, c2);
            }
            sC2[c] = c2;
        }
    }
    __syncthreads();

    if (tid < C) {
        float v = __fadd_rn(__fadd_rn(sC1[tid], sC2[tid]), latent_bias[cand[tid]]);
        sk[tid] = ((unsigned long long)to_key(v) << 32) |
                  (unsigned long long)(0xFFFFFFFFu - (unsigned)cand[tid]);
    }
    __syncthreads();

    // bitonic sort 128 desc (value desc, index asc)
    for (int size = 2; size <= NCAND; size <<= 1) {
        for (int stride = size >> 1; stride > 0; stride >>= 1) {
            if (tid < NCAND) {
                int partner = tid ^ stride;
                if (partner > tid) {
                    bool desc = ((tid & size) == 0);
                    unsigned long long a = sk[tid], b = sk[partner];
                    bool sw = desc ? (a < b) : (a > b);
                    if (sw) { sk[tid] = b; sk[partner] = a; }
                }
            }
            __syncthreads();
        }
    }

    float rv = 0.f; int idx = 0;
    if (tid < TOPK_K) {
        unsigned long long s = sk[tid];
        idx = (int)(0xFFFFFFFFu - (unsigned)(s & 0xFFFFFFFFull));
        float v = from_key((unsigned)(s >> 32));
        rv = fmaxf(v, 0.f);
        float v2 = rv * rv;
        #pragma unroll
        for (int o = 16; o; o >>= 1) v2 += __shfl_down_sync(0xFFFFFFFFu, v2, o);
        if (lane == 0) atomicAdd(&s_sumsq, v2);
    }
    __syncthreads();
    if (tid == 0) {
        float m = __fadd_rn(s_sumsq / (float)D_HID, 1e-8f);
        s_rn = __fdiv_rn(1.0f, __fsqrt_rn(m));
    }
    __syncthreads();

    if (tid < TOPK_K) {
        float fv = rv * s_rn;
        size_t so = (size_t)row * TOPK_K + tid;
        idxOut[so] = (float)idx;
        g_tv[so] = fv;
        g_tix[so] = idx;
        size_t ho = (size_t)row * D_HID + idx;
        hOut[ho] = rv;
        fOut[ho] = fv;
    }
}

// -------------------- K4: sparse decode (4-way ILP accumulators) --------------------------
__global__ __launch_bounds__(192)
void decode_kernel(const float* __restrict__ X,
                   const float* __restrict__ pre_bias,
                   float* __restrict__ out) {
    __shared__ float fv[TOPK_K];
    __shared__ int fx[TOPK_K];
    const int row = blockIdx.x;
    const int tid = threadIdx.x;
    if (tid < TOPK_K) {
        fv[tid] = g_tv[(size_t)row * TOPK_K + tid];
        fx[tid] = g_tix[(size_t)row * TOPK_K + tid];
    }
    __syncthreads();

    const int d = tid * 4;
    float4 a0 = *(const float4*)&pre_bias[d];
    float4 a1 = make_float4(0.f, 0.f, 0.f, 0.f);
    float4 a2 = make_float4(0.f, 0.f, 0.f, 0.f);
    float4 a3 = make_float4(0.f, 0.f, 0.f, 0.f);
    #pragma unroll 4
    for (int k = 0; k < TOPK_K; k += 4) {
        float c0 = fv[k + 0], c1 = fv[k + 1], c2 = fv[k + 2], c3 = fv[k + 3];
        float4 w0 = *(const float4*)&g_WdT[(size_t)fx[k + 0] * D_IN + d];
        float4 w1 = *(const float4*)&g_WdT[(size_t)fx[k + 1] * D_IN + d];
        float4 w2 = *(const float4*)&g_WdT[(size_t)fx[k + 2] * D_IN + d];
        float4 w3 = *(const float4*)&g_WdT[(size_t)fx[k + 3] * D_IN + d];
        a0.x += c0 * w0.x; a0.y += c0 * w0.y; a0.z += c0 * w0.z; a0.w += c0 * w0.w;
        a1.x += c1 * w1.x; a1.y += c1 * w1.y; a1.z += c1 * w1.z; a1.w += c1 * w1.w;
        a2.x += c2 * w2.x; a2.y += c2 * w2.y; a2.z += c2 * w2.z; a2.w += c2 * w2.w;
        a3.x += c3 * w3.x; a3.y += c3 * w3.y; a3.z += c3 * w3.z; a3.w += c3 * w3.w;
    }
    float4 acc = make_float4((a0.x + a1.x) + (a2.x + a3.x),
                             (a0.y + a1.y) + (a2.y + a3.y),
                             (a0.z + a1.z) + (a2.z + a3.z),
                             (a0.w + a1.w) + (a2.w + a3.w));
    float4 xv = *(const float4*)&X[(size_t)row * D_IN + d];
    float4 r = make_float4(xv.x - acc.x, xv.y - acc.y, xv.z - acc.z, xv.w - acc.w);
    *(float4*)&out[XHAT_OFF + (size_t)row * D_IN + d] = acc;
    *(float4*)&out[RES_OFF  + (size_t)row * D_IN + d] = r;
}

// -------------------- launch --------------------
extern "C" void kernel_launch(void* const* d_in, const int* in_sizes, int n_in,
                              void* d_out, int out_size) {
    const float* x           = (const float*)d_in[0];
    const float* W_enc       = (const float*)d_in[1];
    const float* W_dec       = (const float*)d_in[2];
    const float* pre_bias    = (const float*)d_in[3];
    const float* latent_bias = (const float*)d_in[4];
    float* out = (float*)d_out;

    static bool attr_set = false;
    if (!attr_set) {
        cudaFuncSetAttribute(topk_select_kernel, cudaFuncAttributeMaxDynamicSharedMemorySize,
                             D_HID * (int)sizeof(unsigned));
        cudaFuncSetAttribute(gemm_mma_kernel, cudaFuncAttributeMaxDynamicSharedMemorySize,
                             1024 + 2 * BUFB);
        attr_set = true;
    }

    convertX_kernel<<<B_ROWS, 256>>>(x, pre_bias);
    convertW_kernel<<<D_HID, 256>>>(W_enc);
    transpose_kernel<<<dim3(D_HID / 32, D_IN / 32), dim3(32, 8)>>>(W_dec);

    gemm_mma_kernel<<<dim3(D_HID / 128, B_ROWS / 128), 256, 1024 + 2 * BUFB>>>(
        latent_bias, out + PRE_OFF);

    {
        long long n4 = (2LL * B_ROWS * D_HID) / 4;
        zero_kernel<<<8192, 256>>>((float4*)(out + H_OFF), n4);
    }

    topk_select_kernel<<<B_ROWS, 512, D_HID * sizeof(unsigned)>>>(out + PRE_OFF);

    refine_kernel<<<B_ROWS, 256>>>(x, W_enc, latent_bias,
        out + H_OFF, out + F_OFF, out + IDX_OFF);

    decode_kernel<<<B_ROWS, 192>>>(x, pre_bias, out);
}